// round 1
// baseline (speedup 1.0000x reference)
#include <cuda_runtime.h>

#define NJ 24
#define NV 6890

__device__ __constant__ int c_par[NJ] =
    {-1,0,0,0,1,2,3,4,5,6,7,8,9,9,9,12,13,14,16,17,18,19,20,21};

// scratch (no allocations allowed -> __device__ globals)
__device__ float g_Jpose[NJ * 3];
__device__ float g_Jda[NJ * 3];
__device__ float g_A[NJ * 12];   // per joint: 3x4 row-major blend matrix

// ---------------------------------------------------------------------------
// Kernel 1: joint locations J = J_regressor @ (v_template + shapedirs@beta)
// (both for the given beta and for beta = 0, used by the rest pose)
// ---------------------------------------------------------------------------
__global__ void joints_kernel(const float* __restrict__ Jreg,
                              const float* __restrict__ shapedirs,
                              const float* __restrict__ v_template,
                              const float* __restrict__ beta)
{
    const int j = blockIdx.x;
    __shared__ float sb[10];
    if (threadIdx.x < 10) sb[threadIdx.x] = beta[threadIdx.x];
    __syncthreads();

    float accP0 = 0.f, accP1 = 0.f, accP2 = 0.f;
    float accD0 = 0.f, accD1 = 0.f, accD2 = 0.f;

    for (int v = threadIdx.x; v < NV; v += blockDim.x) {
        float r = Jreg[j * NV + v];
        const float* vt = v_template + v * 3;
        const float* sd = shapedirs + v * 30;   // (v, c, k) -> v*30 + c*10 + k
        float d0 = 0.f, d1 = 0.f, d2 = 0.f;
        #pragma unroll
        for (int k = 0; k < 10; k++) {
            float b = sb[k];
            d0 += sd[k]      * b;
            d1 += sd[10 + k] * b;
            d2 += sd[20 + k] * b;
        }
        float t0 = vt[0], t1 = vt[1], t2 = vt[2];
        accD0 += r * t0;        accD1 += r * t1;        accD2 += r * t2;
        accP0 += r * (t0 + d0); accP1 += r * (t1 + d1); accP2 += r * (t2 + d2);
    }

    __shared__ float red[6][256];
    int t = threadIdx.x;
    red[0][t] = accP0; red[1][t] = accP1; red[2][t] = accP2;
    red[3][t] = accD0; red[4][t] = accD1; red[5][t] = accD2;
    __syncthreads();
    for (int s = 128; s > 0; s >>= 1) {
        if (t < s) {
            #pragma unroll
            for (int q = 0; q < 6; q++) red[q][t] += red[q][t + s];
        }
        __syncthreads();
    }
    if (t == 0) {
        g_Jpose[j * 3 + 0] = red[0][0];
        g_Jpose[j * 3 + 1] = red[1][0];
        g_Jpose[j * 3 + 2] = red[2][0];
        g_Jda[j * 3 + 0]   = red[3][0];
        g_Jda[j * 3 + 1]   = red[4][0];
        g_Jda[j * 3 + 2]   = red[5][0];
    }
}

// ---------------------------------------------------------------------------
// Kernel 2: build the 24 blend transforms A_j = pose_j @ inv(da_j)
// ---------------------------------------------------------------------------
__device__ __forceinline__ void matmul4(const float* A, const float* B, float* C)
{
    #pragma unroll
    for (int r = 0; r < 4; r++)
        #pragma unroll
        for (int c = 0; c < 4; c++) {
            float s = 0.f;
            #pragma unroll
            for (int k = 0; k < 4; k++) s += A[r * 4 + k] * B[k * 4 + c];
            C[r * 4 + c] = s;
        }
}

__global__ void transforms_kernel(const float* __restrict__ theta,
                                  const float* __restrict__ da_theta)
{
    __shared__ float L[2][NJ][16];
    __shared__ float G[2][NJ][16];
    __shared__ float Jm[2][NJ][3];
    const int tid = threadIdx.x;

    // phase 1: load joint locations
    if (tid < 48) {
        int w = tid / NJ;            // 0 = pose, 1 = da (rest)
        int j = tid % NJ;
        const float* Jsrc = (w == 0) ? g_Jpose : g_Jda;
        Jm[w][j][0] = Jsrc[j * 3 + 0];
        Jm[w][j][1] = Jsrc[j * 3 + 1];
        Jm[w][j][2] = Jsrc[j * 3 + 2];
    }
    __syncthreads();

    // phase 2: rodrigues + local 4x4 (needs parents' J -> after sync)
    if (tid < 48) {
        int w = tid / NJ;
        int j = tid % NJ;
        const float* th = (w == 0) ? theta : da_theta;
        float r0 = th[j * 3 + 0], r1 = th[j * 3 + 1], r2 = th[j * 3 + 2];
        float n  = sqrtf(r0 * r0 + r1 * r1 + r2 * r2) + 1e-8f;
        float co = cosf(n), si = sinf(n);
        float u0 = r0 / n, u1 = r1 / n, u2 = r2 / n;
        float omc = 1.0f - co;

        float R00 = co + omc * u0 * u0;
        float R01 = omc * u0 * u1 - si * u2;
        float R02 = omc * u0 * u2 + si * u1;
        float R10 = omc * u1 * u0 + si * u2;
        float R11 = co + omc * u1 * u1;
        float R12 = omc * u1 * u2 - si * u0;
        float R20 = omc * u2 * u0 - si * u1;
        float R21 = omc * u2 * u1 + si * u0;
        float R22 = co + omc * u2 * u2;

        int p = c_par[j];
        float jr0, jr1, jr2;
        if (p < 0) { jr0 = Jm[w][j][0]; jr1 = Jm[w][j][1]; jr2 = Jm[w][j][2]; }
        else {
            jr0 = Jm[w][j][0] - Jm[w][p][0];
            jr1 = Jm[w][j][1] - Jm[w][p][1];
            jr2 = Jm[w][j][2] - Jm[w][p][2];
        }
        float* Lw = &L[w][j][0];
        Lw[0] = R00; Lw[1] = R01; Lw[2]  = R02; Lw[3]  = jr0;
        Lw[4] = R10; Lw[5] = R11; Lw[6]  = R12; Lw[7]  = jr1;
        Lw[8] = R20; Lw[9] = R21; Lw[10] = R22; Lw[11] = jr2;
        Lw[12] = 0.f; Lw[13] = 0.f; Lw[14] = 0.f; Lw[15] = 1.f;
    }
    __syncthreads();

    // phase 3: kinematic chain (two independent serial chains)
    if (tid < 2) {
        int w = tid;
        #pragma unroll
        for (int q = 0; q < 16; q++) G[w][0][q] = L[w][0][q];
        for (int i = 1; i < NJ; i++)
            matmul4(&G[w][c_par[i]][0], &L[w][i][0], &G[w][i][0]);
    }
    __syncthreads();

    // phase 4: pack + rigid inverse + A = pose' @ inv(da')
    if (tid < NJ) {
        int j = tid;
        float Rp[9], tp[3], Rd[9], td[3];
        #pragma unroll
        for (int r = 0; r < 3; r++) {
            #pragma unroll
            for (int c = 0; c < 3; c++) {
                Rp[r * 3 + c] = G[0][j][r * 4 + c];
                Rd[r * 3 + c] = G[1][j][r * 4 + c];
            }
            // pack step: t' = t - R @ J  (rest-pose joint translation removed)
            tp[r] = G[0][j][r * 4 + 3] - (Rp[r*3+0] * Jm[0][j][0] +
                                          Rp[r*3+1] * Jm[0][j][1] +
                                          Rp[r*3+2] * Jm[0][j][2]);
            td[r] = G[1][j][r * 4 + 3] - (Rd[r*3+0] * Jm[1][j][0] +
                                          Rd[r*3+1] * Jm[1][j][1] +
                                          Rd[r*3+2] * Jm[1][j][2]);
        }
        // da' is rigid (bottom row exactly [0,0,0,1], rotation orthonormal):
        // inv(da') = [Rd^T | -Rd^T td].  A_R = Rp Rd^T, A_t = tp - A_R td.
        #pragma unroll
        for (int r = 0; r < 3; r++) {
            float a0 = Rp[r*3+0]*Rd[0] + Rp[r*3+1]*Rd[1] + Rp[r*3+2]*Rd[2];
            float a1 = Rp[r*3+0]*Rd[3] + Rp[r*3+1]*Rd[4] + Rp[r*3+2]*Rd[5];
            float a2 = Rp[r*3+0]*Rd[6] + Rp[r*3+1]*Rd[7] + Rp[r*3+2]*Rd[8];
            float at = tp[r] - (a0 * td[0] + a1 * td[1] + a2 * td[2]);
            g_A[j * 12 + r * 4 + 0] = a0;
            g_A[j * 12 + r * 4 + 1] = a1;
            g_A[j * 12 + r * 4 + 2] = a2;
            g_A[j * 12 + r * 4 + 3] = at;
        }
    }
}

// ---------------------------------------------------------------------------
// Kernel 3: the big LBS pass. 4 points/thread, f32x2 packed FMAs.
// ---------------------------------------------------------------------------
typedef unsigned long long u64;

__device__ __forceinline__ u64 pack2(float lo, float hi) {
    u64 d; asm("mov.b64 %0, {%1, %2};" : "=l"(d) : "f"(lo), "f"(hi)); return d;
}
__device__ __forceinline__ u64 fma2(u64 a, u64 b, u64 c) {
    u64 d; asm("fma.rn.f32x2 %0, %1, %2, %3;" : "=l"(d) : "l"(a), "l"(b), "l"(c));
    return d;
}
__device__ __forceinline__ float2 unpack2(u64 v) {
    float lo, hi; asm("mov.b64 {%0, %1}, %2;" : "=f"(lo), "=f"(hi) : "l"(v));
    return make_float2(lo, hi);
}

__global__ void __launch_bounds__(256) lbs_kernel(const float* __restrict__ pts,
                                                  const float* __restrict__ wts,
                                                  float* __restrict__ out,
                                                  int N)
{
    // coefficients duplicated as (a,a) f32x2 for broadcast LDS.64
    __shared__ u64 sA[NJ * 12];
    for (int i = threadIdx.x; i < NJ * 12; i += blockDim.x) {
        float a = g_A[i];
        sA[i] = pack2(a, a);
    }
    __syncthreads();

    long long base = ((long long)blockIdx.x * blockDim.x + threadIdx.x) * 4;
    if (base >= N) return;

    if (base + 4 <= N) {
        const float4 x4 = *(const float4*)(pts + base);
        const float4 y4 = *(const float4*)(pts + (long long)N + base);
        const float4 z4 = *(const float4*)(pts + 2LL * N + base);

        u64 s01[12], s23[12];
        #pragma unroll
        for (int k = 0; k < 12; k++) { s01[k] = 0ull; s23[k] = 0ull; }

        #pragma unroll 4
        for (int j = 0; j < NJ; j++) {
            const float4 wv = *(const float4*)(wts + (long long)j * N + base);
            u64 w01 = pack2(wv.x, wv.y);
            u64 w23 = pack2(wv.z, wv.w);
            #pragma unroll
            for (int k = 0; k < 12; k++) {
                u64 a = sA[j * 12 + k];
                s01[k] = fma2(w01, a, s01[k]);
                s23[k] = fma2(w23, a, s23[k]);
            }
        }

        u64 x01 = pack2(x4.x, x4.y), x23 = pack2(x4.z, x4.w);
        u64 y01 = pack2(y4.x, y4.y), y23 = pack2(y4.z, y4.w);
        u64 z01 = pack2(z4.x, z4.y), z23 = pack2(z4.z, z4.w);

        #pragma unroll
        for (int c = 0; c < 3; c++) {
            u64 r01 = fma2(s01[c*4+0], x01,
                      fma2(s01[c*4+1], y01,
                      fma2(s01[c*4+2], z01, s01[c*4+3])));
            u64 r23 = fma2(s23[c*4+0], x23,
                      fma2(s23[c*4+1], y23,
                      fma2(s23[c*4+2], z23, s23[c*4+3])));
            float2 a = unpack2(r01), b = unpack2(r23);
            *(float4*)(out + (long long)c * N + base) =
                make_float4(a.x, a.y, b.x, b.y);
        }
    } else {
        // scalar tail (never taken for N % 4 == 0, kept for safety)
        for (long long n = base; n < N; n++) {
            float x = pts[n], y = pts[(long long)N + n], z = pts[2LL * N + n];
            float o0 = 0.f, o1 = 0.f, o2 = 0.f;
            for (int j = 0; j < NJ; j++) {
                float w = wts[(long long)j * N + n];
                const float* A = &g_A[j * 12];
                o0 += w * (A[0] * x + A[1] * y + A[2]  * z + A[3]);
                o1 += w * (A[4] * x + A[5] * y + A[6]  * z + A[7]);
                o2 += w * (A[8] * x + A[9] * y + A[10] * z + A[11]);
            }
            out[n] = o0;
            out[(long long)N + n] = o1;
            out[2LL * N + n] = o2;
        }
    }
}

// ---------------------------------------------------------------------------
extern "C" void kernel_launch(void* const* d_in, const int* in_sizes, int n_in,
                              void* d_out, int out_size)
{
    const float* pts       = (const float*)d_in[0];  // (3, N)
    const float* wts       = (const float*)d_in[1];  // (24, N)
    const float* beta      = (const float*)d_in[2];  // (10,)
    const float* theta     = (const float*)d_in[3];  // (24, 3)
    const float* da_theta  = (const float*)d_in[4];  // (24, 3)
    const float* shapedirs = (const float*)d_in[5];  // (6890, 3, 10)
    const float* v_templ   = (const float*)d_in[6];  // (6890, 3)
    const float* Jreg      = (const float*)d_in[7];  // (24, 6890)
    float* out = (float*)d_out;                      // (1, 3, N)

    const int N = in_sizes[0] / 3;

    joints_kernel<<<NJ, 256>>>(Jreg, shapedirs, v_templ, beta);
    transforms_kernel<<<1, 64>>>(theta, da_theta);

    long long nthreads = ((long long)N + 3) / 4;
    int blocks = (int)((nthreads + 255) / 256);
    lbs_kernel<<<blocks, 256>>>(pts, wts, out, N);
}

// round 3
// speedup vs baseline: 1.7722x; 1.7722x over previous
#include <cuda_runtime.h>

#define NJ 24
#define NV 6890
#define JSPLIT 8
#define JCHUNK 862   // ceil(6890/8)

__device__ __constant__ int c_par[NJ] =
    {-1,0,0,0,1,2,3,4,5,6,7,8,9,9,9,12,13,14,16,17,18,19,20,21};

// scratch (no allocations allowed -> __device__ globals)
__device__ float g_part[NJ][JSPLIT][6];  // per-(joint,slice) partial sums
__device__ float g_A[NJ * 12];           // per joint: 3x4 row-major blend matrix

// ---------------------------------------------------------------------------
// Kernel 1: partial joint sums.  grid = (JSPLIT, NJ), block = 128.
// Each block reduces its vertex slice for one joint, for BOTH beta and beta=0.
// ---------------------------------------------------------------------------
__global__ void __launch_bounds__(128) joints_kernel(
    const float* __restrict__ Jreg,
    const float* __restrict__ shapedirs,
    const float* __restrict__ v_template,
    const float* __restrict__ beta)
{
    const int s = blockIdx.x;
    const int j = blockIdx.y;
    __shared__ float sb[10];
    if (threadIdx.x < 10) sb[threadIdx.x] = beta[threadIdx.x];
    __syncthreads();

    const int v0 = s * JCHUNK;
    const int v1 = min(v0 + JCHUNK, NV);

    float accP0 = 0.f, accP1 = 0.f, accP2 = 0.f;
    float accD0 = 0.f, accD1 = 0.f, accD2 = 0.f;

    for (int v = v0 + threadIdx.x; v < v1; v += 128) {
        float r = Jreg[j * NV + v];
        const float* vt = v_template + v * 3;
        const float* sd = shapedirs + v * 30;   // (v, c, k) -> v*30 + c*10 + k
        float d0 = 0.f, d1 = 0.f, d2 = 0.f;
        #pragma unroll
        for (int k = 0; k < 10; k++) {
            float b = sb[k];
            d0 += sd[k]      * b;
            d1 += sd[10 + k] * b;
            d2 += sd[20 + k] * b;
        }
        float t0 = vt[0], t1 = vt[1], t2 = vt[2];
        accD0 += r * t0;        accD1 += r * t1;        accD2 += r * t2;
        accP0 += r * (t0 + d0); accP1 += r * (t1 + d1); accP2 += r * (t2 + d2);
    }

    __shared__ float red[6][128];
    int t = threadIdx.x;
    red[0][t] = accP0; red[1][t] = accP1; red[2][t] = accP2;
    red[3][t] = accD0; red[4][t] = accD1; red[5][t] = accD2;
    __syncthreads();
    for (int w = 64; w > 0; w >>= 1) {
        if (t < w) {
            #pragma unroll
            for (int q = 0; q < 6; q++) red[q][t] += red[q][t + w];
        }
        __syncthreads();
    }
    if (t < 6) g_part[j][s][t] = red[t][0];
}

// ---------------------------------------------------------------------------
// Kernel 2: build the 24 blend transforms A_j = pose_j @ inv(da_j)
// ---------------------------------------------------------------------------
__device__ __forceinline__ void matmul4(const float* A, const float* B, float* C)
{
    #pragma unroll
    for (int r = 0; r < 4; r++)
        #pragma unroll
        for (int c = 0; c < 4; c++) {
            float s = 0.f;
            #pragma unroll
            for (int k = 0; k < 4; k++) s += A[r * 4 + k] * B[k * 4 + c];
            C[r * 4 + c] = s;
        }
}

__global__ void transforms_kernel(const float* __restrict__ theta,
                                  const float* __restrict__ da_theta)
{
    __shared__ float L[2][NJ][16];
    __shared__ float G[2][NJ][16];
    __shared__ float Jm[2][NJ][3];
    const int tid = threadIdx.x;

    // phase 0: reduce the per-slice partials -> joint locations
    if (tid < 48) {
        int w = tid / NJ;            // 0 = pose, 1 = da (rest)
        int j = tid % NJ;
        float a0 = 0.f, a1 = 0.f, a2 = 0.f;
        #pragma unroll
        for (int s = 0; s < JSPLIT; s++) {
            a0 += g_part[j][s][w * 3 + 0];
            a1 += g_part[j][s][w * 3 + 1];
            a2 += g_part[j][s][w * 3 + 2];
        }
        Jm[w][j][0] = a0; Jm[w][j][1] = a1; Jm[w][j][2] = a2;
    }
    __syncthreads();

    // phase 1: rodrigues + local 4x4 (needs parents' J -> after sync)
    if (tid < 48) {
        int w = tid / NJ;
        int j = tid % NJ;
        const float* th = (w == 0) ? theta : da_theta;
        float r0 = th[j * 3 + 0], r1 = th[j * 3 + 1], r2 = th[j * 3 + 2];
        float n  = sqrtf(r0 * r0 + r1 * r1 + r2 * r2) + 1e-8f;
        float co = cosf(n), si = sinf(n);
        float u0 = r0 / n, u1 = r1 / n, u2 = r2 / n;
        float omc = 1.0f - co;

        float R00 = co + omc * u0 * u0;
        float R01 = omc * u0 * u1 - si * u2;
        float R02 = omc * u0 * u2 + si * u1;
        float R10 = omc * u1 * u0 + si * u2;
        float R11 = co + omc * u1 * u1;
        float R12 = omc * u1 * u2 - si * u0;
        float R20 = omc * u2 * u0 - si * u1;
        float R21 = omc * u2 * u1 + si * u0;
        float R22 = co + omc * u2 * u2;

        int p = c_par[j];
        float jr0, jr1, jr2;
        if (p < 0) { jr0 = Jm[w][j][0]; jr1 = Jm[w][j][1]; jr2 = Jm[w][j][2]; }
        else {
            jr0 = Jm[w][j][0] - Jm[w][p][0];
            jr1 = Jm[w][j][1] - Jm[w][p][1];
            jr2 = Jm[w][j][2] - Jm[w][p][2];
        }
        float* Lw = &L[w][j][0];
        Lw[0] = R00; Lw[1] = R01; Lw[2]  = R02; Lw[3]  = jr0;
        Lw[4] = R10; Lw[5] = R11; Lw[6]  = R12; Lw[7]  = jr1;
        Lw[8] = R20; Lw[9] = R21; Lw[10] = R22; Lw[11] = jr2;
        Lw[12] = 0.f; Lw[13] = 0.f; Lw[14] = 0.f; Lw[15] = 1.f;
    }
    __syncthreads();

    // phase 2: kinematic chain (two independent serial chains)
    if (tid < 2) {
        int w = tid;
        #pragma unroll
        for (int q = 0; q < 16; q++) G[w][0][q] = L[w][0][q];
        for (int i = 1; i < NJ; i++)
            matmul4(&G[w][c_par[i]][0], &L[w][i][0], &G[w][i][0]);
    }
    __syncthreads();

    // phase 3: pack + rigid inverse + A = pose' @ inv(da')
    if (tid < NJ) {
        int j = tid;
        float Rp[9], tp[3], Rd[9], td[3];
        #pragma unroll
        for (int r = 0; r < 3; r++) {
            #pragma unroll
            for (int c = 0; c < 3; c++) {
                Rp[r * 3 + c] = G[0][j][r * 4 + c];
                Rd[r * 3 + c] = G[1][j][r * 4 + c];
            }
            // pack step: t' = t - R @ J  (rest-pose joint translation removed)
            tp[r] = G[0][j][r * 4 + 3] - (Rp[r*3+0] * Jm[0][j][0] +
                                          Rp[r*3+1] * Jm[0][j][1] +
                                          Rp[r*3+2] * Jm[0][j][2]);
            td[r] = G[1][j][r * 4 + 3] - (Rd[r*3+0] * Jm[1][j][0] +
                                          Rd[r*3+1] * Jm[1][j][1] +
                                          Rd[r*3+2] * Jm[1][j][2]);
        }
        // da' is rigid: inv(da') = [Rd^T | -Rd^T td].  A_R = Rp Rd^T, A_t = tp - A_R td.
        #pragma unroll
        for (int r = 0; r < 3; r++) {
            float a0 = Rp[r*3+0]*Rd[0] + Rp[r*3+1]*Rd[1] + Rp[r*3+2]*Rd[2];
            float a1 = Rp[r*3+0]*Rd[3] + Rp[r*3+1]*Rd[4] + Rp[r*3+2]*Rd[5];
            float a2 = Rp[r*3+0]*Rd[6] + Rp[r*3+1]*Rd[7] + Rp[r*3+2]*Rd[8];
            float at = tp[r] - (a0 * td[0] + a1 * td[1] + a2 * td[2]);
            g_A[j * 12 + r * 4 + 0] = a0;
            g_A[j * 12 + r * 4 + 1] = a1;
            g_A[j * 12 + r * 4 + 2] = a2;
            g_A[j * 12 + r * 4 + 3] = at;
        }
    }
}

// ---------------------------------------------------------------------------
// Kernel 3: the big LBS pass. 4 points/thread, f32x2 packed FMAs,
// direct  o += w * (A_j p)  accumulation (only 6 u64 accumulators).
// ---------------------------------------------------------------------------
typedef unsigned long long u64;

__device__ __forceinline__ u64 pack2(float lo, float hi) {
    u64 d; asm("mov.b64 %0, {%1, %2};" : "=l"(d) : "f"(lo), "f"(hi)); return d;
}
__device__ __forceinline__ u64 fma2(u64 a, u64 b, u64 c) {
    u64 d; asm("fma.rn.f32x2 %0, %1, %2, %3;" : "=l"(d) : "l"(a), "l"(b), "l"(c));
    return d;
}
__device__ __forceinline__ float2 unpack2(u64 v) {
    float lo, hi; asm("mov.b64 {%0, %1}, %2;" : "=f"(lo), "=f"(hi) : "l"(v));
    return make_float2(lo, hi);
}

__global__ void __launch_bounds__(256) lbs_kernel(const float* __restrict__ pts,
                                                  const float* __restrict__ wts,
                                                  float* __restrict__ out,
                                                  int N)
{
    // coefficients duplicated as (a,a) f32x2 for broadcast LDS.64
    __shared__ u64 sA[NJ * 12];
    for (int i = threadIdx.x; i < NJ * 12; i += blockDim.x) {
        float a = g_A[i];
        sA[i] = pack2(a, a);
    }
    __syncthreads();

    long long base = ((long long)blockIdx.x * blockDim.x + threadIdx.x) * 4;
    if (base >= N) return;

    if (base + 4 <= N) {
        const float4 x4 = *(const float4*)(pts + base);
        const float4 y4 = *(const float4*)(pts + (long long)N + base);
        const float4 z4 = *(const float4*)(pts + 2LL * N + base);

        u64 x01 = pack2(x4.x, x4.y), x23 = pack2(x4.z, x4.w);
        u64 y01 = pack2(y4.x, y4.y), y23 = pack2(y4.z, y4.w);
        u64 z01 = pack2(z4.x, z4.y), z23 = pack2(z4.z, z4.w);

        u64 o01[3], o23[3];
        #pragma unroll
        for (int c = 0; c < 3; c++) { o01[c] = 0ull; o23[c] = 0ull; }

        #pragma unroll
        for (int j = 0; j < NJ; j++) {
            const float4 wv = *(const float4*)(wts + (long long)j * N + base);
            u64 w01 = pack2(wv.x, wv.y);
            u64 w23 = pack2(wv.z, wv.w);
            #pragma unroll
            for (int c = 0; c < 3; c++) {
                u64 a0 = sA[j * 12 + c * 4 + 0];
                u64 a1 = sA[j * 12 + c * 4 + 1];
                u64 a2 = sA[j * 12 + c * 4 + 2];
                u64 a3 = sA[j * 12 + c * 4 + 3];
                u64 r01 = fma2(a0, x01, fma2(a1, y01, fma2(a2, z01, a3)));
                u64 r23 = fma2(a0, x23, fma2(a1, y23, fma2(a2, z23, a3)));
                o01[c] = fma2(w01, r01, o01[c]);
                o23[c] = fma2(w23, r23, o23[c]);
            }
        }

        #pragma unroll
        for (int c = 0; c < 3; c++) {
            float2 a = unpack2(o01[c]), b = unpack2(o23[c]);
            *(float4*)(out + (long long)c * N + base) =
                make_float4(a.x, a.y, b.x, b.y);
        }
    } else {
        // scalar tail (never taken for N % 4 == 0, kept for safety)
        for (long long n = base; n < N; n++) {
            float x = pts[n], y = pts[(long long)N + n], z = pts[2LL * N + n];
            float o0 = 0.f, o1 = 0.f, o2 = 0.f;
            for (int j = 0; j < NJ; j++) {
                float w = wts[(long long)j * N + n];
                const float* A = &g_A[j * 12];
                o0 += w * (A[0] * x + A[1] * y + A[2]  * z + A[3]);
                o1 += w * (A[4] * x + A[5] * y + A[6]  * z + A[7]);
                o2 += w * (A[8] * x + A[9] * y + A[10] * z + A[11]);
            }
            out[n] = o0;
            out[(long long)N + n] = o1;
            out[2LL * N + n] = o2;
        }
    }
}

// ---------------------------------------------------------------------------
extern "C" void kernel_launch(void* const* d_in, const int* in_sizes, int n_in,
                              void* d_out, int out_size)
{
    const float* pts       = (const float*)d_in[0];  // (3, N)
    const float* wts       = (const float*)d_in[1];  // (24, N)
    const float* beta      = (const float*)d_in[2];  // (10,)
    const float* theta     = (const float*)d_in[3];  // (24, 3)
    const float* da_theta  = (const float*)d_in[4];  // (24, 3)
    const float* shapedirs = (const float*)d_in[5];  // (6890, 3, 10)
    const float* v_templ   = (const float*)d_in[6];  // (6890, 3)
    const float* Jreg      = (const float*)d_in[7];  // (24, 6890)
    float* out = (float*)d_out;                      // (1, 3, N)

    const int N = in_sizes[0] / 3;

    dim3 jgrid(JSPLIT, NJ);
    joints_kernel<<<jgrid, 128>>>(Jreg, shapedirs, v_templ, beta);
    transforms_kernel<<<1, 64>>>(theta, da_theta);

    long long nthreads = ((long long)N + 3) / 4;
    int blocks = (int)((nthreads + 255) / 256);
    lbs_kernel<<<blocks, 256>>>(pts, wts, out, N);
}